// round 7
// baseline (speedup 1.0000x reference)
#include <cuda_runtime.h>
#include <cstdint>

// Problem constants (fixed by the dataset).
#define E_EDGES 8192u
#define N_NODES 4096u
#define TOTAL (1u << 26)         // E*E elements
#define KOUT 16384               // K*E output rows
#define NWORDS (1u << 20)        // 2^26 bits / 64

// ---------------- device scratch (static allocations only) ----------------
__device__ unsigned g_cnt_d[N_NODES];
__device__ unsigned g_deg[N_NODES];
__device__ unsigned g_off[N_NODES + 1];
__device__ unsigned g_cursor[N_NODES];
__device__ int g_adj[E_EDGES];
__device__ unsigned g_T;                        // mantissa threshold, 0..2^23
__device__ unsigned long long g_bitmap[NWORDS]; // 8 MB kept-bitmap over t in [0, 2^26)
__device__ unsigned g_blockcnt[1024];

// ------- threefry-2x32, key = (0, 42), partitionable layout -------
// Per element t: x = (hi(t)=0, lo(t)=t), bits = out0 ^ out1.  (validated exact)
#define TF_ROUND(r) { x0 += x1; x1 = __funnelshift_l(x1, x1, (r)) ^ x0; }

__device__ __forceinline__ unsigned tf_bits(unsigned t) {
    const unsigned ks0 = 0u, ks1 = 42u, ks2 = 0x1BD11BDAu ^ 42u;
    unsigned x0 = 0u;            // counts_hi + ks0
    unsigned x1 = t + ks1;       // counts_lo + ks1
    TF_ROUND(13) TF_ROUND(15) TF_ROUND(26) TF_ROUND(6)
    x0 += ks1; x1 += ks2 + 1u;
    TF_ROUND(17) TF_ROUND(29) TF_ROUND(16) TF_ROUND(24)
    x0 += ks2; x1 += ks0 + 2u;
    TF_ROUND(13) TF_ROUND(15) TF_ROUND(26) TF_ROUND(6)
    x0 += ks0; x1 += ks1 + 3u;
    TF_ROUND(17) TF_ROUND(29) TF_ROUND(16) TF_ROUND(24)
    x0 += ks1; x1 += ks2 + 4u;
    TF_ROUND(13) TF_ROUND(15) TF_ROUND(26) TF_ROUND(6)
    x0 += ks2; x1 += ks0 + 5u;
    return x0 ^ x1;
}

// ---------------- kernel 1: zero scratch ----------------
__global__ void k_zero() {
    unsigned tid = blockIdx.x * blockDim.x + threadIdx.x;  // 2^20 threads
    g_bitmap[tid] = 0ull;
    if (tid < N_NODES) { g_cnt_d[tid] = 0u; g_deg[tid] = 0u; g_cursor[tid] = 0u; }
}

// ---------------- kernel 2: fused graph setup (1 block, 1024 threads) -------
__global__ void __launch_bounds__(1024) k_setup(const int* __restrict__ src,
                                                const int* __restrict__ dst) {
    __shared__ unsigned s[1024];
    __shared__ unsigned long long s_nn[32];
    unsigned t = threadIdx.x;

    // Phase A: histograms
    for (unsigned e = t; e < E_EDGES; e += 1024) {
        unsigned d = (unsigned)dst[e], ss = (unsigned)src[e];
        if (d < N_NODES) atomicAdd(&g_cnt_d[d], 1u);
        if (ss < N_NODES) atomicAdd(&g_deg[ss], 1u);
    }
    __syncthreads();

    // Phase B: exclusive scan of degrees (4 per thread)
    unsigned v[4], sum = 0;
#pragma unroll
    for (int k = 0; k < 4; k++) { v[k] = g_deg[t * 4 + k]; sum += v[k]; }
    s[t] = sum; __syncthreads();
    for (int d = 1; d < 1024; d <<= 1) {
        unsigned a = (t >= (unsigned)d) ? s[t - d] : 0u;
        __syncthreads();
        s[t] += a;
        __syncthreads();
    }
    unsigned excl = (t == 0) ? 0u : s[t - 1];
#pragma unroll
    for (int k = 0; k < 4; k++) { g_off[t * 4 + k] = excl; excl += v[k]; }
    if (t == 1023) g_off[N_NODES] = excl;
    __syncthreads();

    // Phase C: fill adjacency (CSR by src)
    for (unsigned e = t; e < E_EDGES; e += 1024) {
        unsigned ss = (unsigned)src[e];
        if (ss < N_NODES) {
            unsigned pos = atomicAdd(&g_cursor[ss], 1u);
            unsigned slot = g_off[ss] + pos;
            if (slot < E_EDGES) g_adj[slot] = dst[e];
        }
    }
    __syncthreads();

    // Phase D: num_negatives = sum_s deg(s) * (E - X_s),
    //          X_s = sum of cnt_d over distinct B(s) = {s} ∪ adj(s)
    unsigned long long nn = 0ull;
    for (unsigned ss = t; ss < N_NODES; ss += 1024) {
        unsigned o = g_off[ss], e = g_off[ss + 1];
        unsigned d = e - o;
        if (d == 0) continue;
        unsigned X = g_cnt_d[ss];
        for (unsigned a = o; a < e; a++) {
            int vtx = g_adj[a];
            if (vtx == (int)ss) continue;
            bool dup = false;
            for (unsigned b = o; b < a; b++) if (g_adj[b] == vtx) { dup = true; break; }
            if (!dup && (unsigned)vtx < N_NODES) X += g_cnt_d[vtx];
        }
        nn += (unsigned long long)d * (unsigned long long)(E_EDGES - X);
    }
    // block reduce nn
    for (int off = 16; off > 0; off >>= 1)
        nn += __shfl_down_sync(0xFFFFFFFFu, nn, off);
    if ((t & 31u) == 0u) s_nn[t >> 5] = nn;
    __syncthreads();
    if (t == 0) {
        unsigned long long total = 0ull;
        for (int w = 0; w < 32; w++) total += s_nn[w];
        // Phase E: threshold
        unsigned long long ratio = total >> 13;  // // E
        unsigned T;
        if (ratio == 0ull) {
            T = 1u << 23;
        } else {
            float p = __fdiv_rn(2.0f, (float)ratio);   // matches jnp float32 divide
            double pt = (double)p * 8388608.0;          // p * 2^23 (exact)
            double ct = ceil(pt);
            T = (ct >= 8388608.0) ? (1u << 23) : (unsigned)ct;
        }
        g_T = T;
    }
}

// ---------------- kernel 3: main scan (2^26 threefry evals) ----------------
__device__ __forceinline__ void try_keep(unsigned t,
                                         const int* __restrict__ src,
                                         const int* __restrict__ dst) {
    unsigned i = t >> 13, j = t & (E_EDGES - 1u);
    int s = src[i];
    int dj = dst[j];
    if (dj == s) return;
    unsigned o = g_off[s], e = g_off[s + 1];
    for (unsigned k = o; k < e; k++)
        if (g_adj[k] == dj) return;
    atomicOr(&g_bitmap[t >> 6], 1ull << (t & 63u));
}

#define PER 8
__global__ void __launch_bounds__(256) k_main(const int* __restrict__ src,
                                              const int* __restrict__ dst) {
    unsigned T = g_T;
    unsigned base = (blockIdx.x * 256u + threadIdx.x) * PER;
#pragma unroll
    for (int u = 0; u < PER; u++) {
        unsigned c = base + u;
        unsigned m = tf_bits(c) >> 9;
        if (m < T) try_keep(c, src, dst);
    }
}

// ------- kernel 4: per-block popcounts + output padding init (fused) -------
__global__ void k_count(const int* __restrict__ src, const int* __restrict__ dst,
                        float* __restrict__ out, int out_size) {
    __shared__ unsigned s[256];
    unsigned wbase = blockIdx.x * 1024u + threadIdx.x * 4u;
    unsigned c = 0;
#pragma unroll
    for (int k = 0; k < 4; k++) c += __popcll(g_bitmap[wbase + k]);
    s[threadIdx.x] = c; __syncthreads();
    for (int d = 128; d > 0; d >>= 1) {
        if (threadIdx.x < (unsigned)d) s[threadIdx.x] += s[threadIdx.x + d];
        __syncthreads();
    }
    if (threadIdx.x == 0) g_blockcnt[blockIdx.x] = s[0];

    // fused padding init: indices never reached by emit keep pad value
    unsigned q = blockIdx.x * 256u + threadIdx.x;
    if (q < KOUT) {
        if ((int)q < out_size) out[q] = (float)src[0];
        if ((int)(KOUT + q) < out_size) out[KOUT + q] = (float)dst[0];
    }
}

// ------- kernel 5: ordered emit (computes its own global prefix) -------
__global__ void k_emit(const int* __restrict__ src, const int* __restrict__ dst,
                       float* __restrict__ out, int out_size) {
    __shared__ unsigned s[256];
    __shared__ unsigned s_pre[256];
    unsigned t = threadIdx.x;

    // global exclusive prefix over earlier blocks
    unsigned pre = 0;
    for (unsigned j = t; j < blockIdx.x; j += 256) pre += g_blockcnt[j];
    s_pre[t] = pre; __syncthreads();
    for (int d = 128; d > 0; d >>= 1) {
        if (t < (unsigned)d) s_pre[t] += s_pre[t + d];
        __syncthreads();
    }
    unsigned blockoff = s_pre[0];
    __syncthreads();

    unsigned wbase = blockIdx.x * 1024u + t * 4u;
    unsigned long long w[4];
    unsigned c = 0;
#pragma unroll
    for (int k = 0; k < 4; k++) { w[k] = g_bitmap[wbase + k]; c += __popcll(w[k]); }
    s[t] = c; __syncthreads();
    for (int d = 1; d < 256; d <<= 1) {
        unsigned a = (t >= (unsigned)d) ? s[t - d] : 0u;
        __syncthreads();
        s[t] += a;
        __syncthreads();
    }
    unsigned pos = blockoff + s[t] - c;  // global exclusive prefix for this thread
    if (c == 0) return;
#pragma unroll
    for (int k = 0; k < 4; k++) {
        unsigned long long ww = w[k];
        unsigned wi = wbase + k;
        while (ww) {
            int b = __ffsll((long long)ww) - 1;
            unsigned tt = wi * 64u + (unsigned)b;
            if (pos < KOUT) {
                if ((int)pos < out_size) out[pos] = (float)src[tt >> 13];
                if ((int)(KOUT + pos) < out_size) out[KOUT + pos] = (float)dst[tt & (E_EDGES - 1u)];
            }
            pos++;
            ww &= ww - 1ull;
        }
    }
}

// ---------------- launch ----------------
extern "C" void kernel_launch(void* const* d_in, const int* in_sizes, int n_in,
                              void* d_out, int out_size) {
    // Input selection by element count (node_feature has 262144 elems).
    const int* src;
    const int* dst;
    if (n_in >= 3 && in_sizes[0] == (int)E_EDGES) {
        dst = (const int*)d_in[0];   // alphabetical: edge_dst first
        src = (const int*)d_in[1];
    } else {
        src = (const int*)d_in[1];   // dict order: node_feature first
        dst = (const int*)d_in[2];
    }
    float* out = (float*)d_out;

    k_zero<<<NWORDS / 512, 512>>>();
    k_setup<<<1, 1024>>>(src, dst);
    k_main<<<TOTAL / (256 * PER), 256>>>(src, dst);
    k_count<<<1024, 256>>>(src, dst, out, out_size);
    k_emit<<<1024, 256>>>(src, dst, out, out_size);
}

// round 8
// speedup vs baseline: 1.4616x; 1.4616x over previous
#include <cuda_runtime.h>
#include <cstdint>

// Problem constants (fixed by the dataset).
#define E_EDGES 8192u
#define N_NODES 4096u
#define TOTAL (1u << 26)         // E*E elements
#define KOUT 16384               // K*E output rows
#define NWORDS (1u << 20)        // 2^26 bits / 64
#define NCHUNK 16                // k_main split factor

// ---------------- device scratch (static allocations only) ----------------
__device__ unsigned g_cnt_d[N_NODES];
__device__ unsigned g_deg[N_NODES];
__device__ unsigned g_off[N_NODES + 1];
__device__ unsigned g_cursor[N_NODES];
__device__ int g_adj[E_EDGES];
__device__ unsigned long long g_numneg;
__device__ unsigned g_T;                       // mantissa threshold, 0..2^23
__device__ unsigned long long g_bitmap[NWORDS]; // 8 MB kept-bitmap over t in [0, 2^26)
__device__ unsigned g_blockcnt[1024];
__device__ unsigned g_blockoff[1024];

// ------- threefry-2x32, key = (0, 42), partitionable layout (validated) -------
#define TF_ROUND(r) { x0 += x1; x1 = __funnelshift_l(x1, x1, (r)) ^ x0; }

__device__ __forceinline__ unsigned tf_bits(unsigned t) {
    const unsigned ks0 = 0u, ks1 = 42u, ks2 = 0x1BD11BDAu ^ 42u;
    unsigned x0 = 0u;            // counts_hi + ks0
    unsigned x1 = t + ks1;       // counts_lo + ks1
    TF_ROUND(13) TF_ROUND(15) TF_ROUND(26) TF_ROUND(6)
    x0 += ks1; x1 += ks2 + 1u;
    TF_ROUND(17) TF_ROUND(29) TF_ROUND(16) TF_ROUND(24)
    x0 += ks2; x1 += ks0 + 2u;
    TF_ROUND(13) TF_ROUND(15) TF_ROUND(26) TF_ROUND(6)
    x0 += ks0; x1 += ks1 + 3u;
    TF_ROUND(17) TF_ROUND(29) TF_ROUND(16) TF_ROUND(24)
    x0 += ks1; x1 += ks2 + 4u;
    TF_ROUND(13) TF_ROUND(15) TF_ROUND(26) TF_ROUND(6)
    x0 += ks2; x1 += ks0 + 5u;
    return x0 ^ x1;
}

// ---------------- setup kernels (R6-scored versions) ----------------
__global__ void k_zero() {
    unsigned tid = blockIdx.x * blockDim.x + threadIdx.x;  // 2^20 threads
    g_bitmap[tid] = 0ull;
    if (tid < N_NODES) { g_cnt_d[tid] = 0u; g_deg[tid] = 0u; g_cursor[tid] = 0u; }
    if (tid == 0) g_numneg = 0ull;
}

__global__ void k_hist(const int* __restrict__ src, const int* __restrict__ dst) {
    unsigned e = blockIdx.x * blockDim.x + threadIdx.x;
    if (e < E_EDGES) {
        unsigned d = (unsigned)dst[e], s = (unsigned)src[e];
        if (d < N_NODES) atomicAdd(&g_cnt_d[d], 1u);
        if (s < N_NODES) atomicAdd(&g_deg[s], 1u);
    }
}

__global__ void k_scan_deg() {  // 1 block, 1024 threads, 4 elems/thread
    __shared__ unsigned s[1024];
    unsigned t = threadIdx.x;
    unsigned v[4], sum = 0;
#pragma unroll
    for (int k = 0; k < 4; k++) { v[k] = g_deg[t * 4 + k]; sum += v[k]; }
    s[t] = sum; __syncthreads();
    for (int d = 1; d < 1024; d <<= 1) {
        unsigned a = (t >= (unsigned)d) ? s[t - d] : 0u;
        __syncthreads();
        s[t] += a;
        __syncthreads();
    }
    unsigned excl = (t == 0) ? 0u : s[t - 1];
#pragma unroll
    for (int k = 0; k < 4; k++) { g_off[t * 4 + k] = excl; excl += v[k]; }
    if (t == 1023) g_off[N_NODES] = excl;
}

__global__ void k_fill(const int* __restrict__ src, const int* __restrict__ dst) {
    unsigned e = blockIdx.x * blockDim.x + threadIdx.x;
    if (e < E_EDGES) {
        unsigned s = (unsigned)src[e];
        if (s < N_NODES) {
            unsigned pos = atomicAdd(&g_cursor[s], 1u);
            unsigned slot = g_off[s] + pos;
            if (slot < E_EDGES) g_adj[slot] = dst[e];
        }
    }
}

__global__ void k_rowcount() {
    unsigned s = blockIdx.x * blockDim.x + threadIdx.x;
    if (s >= N_NODES) return;
    unsigned o = g_off[s], e = g_off[s + 1];
    unsigned d = e - o;
    if (d == 0) return;
    unsigned X = g_cnt_d[s];
    for (unsigned a = o; a < e; a++) {
        int v = g_adj[a];
        if (v == (int)s) continue;
        bool dup = false;
        for (unsigned b = o; b < a; b++) if (g_adj[b] == v) { dup = true; break; }
        if (!dup && (unsigned)v < N_NODES) X += g_cnt_d[v];
    }
    atomicAdd(&g_numneg, (unsigned long long)d * (unsigned long long)(E_EDGES - X));
}

__global__ void k_thresh() {
    unsigned long long nn = g_numneg;
    unsigned long long ratio = nn >> 13;  // // E
    unsigned T;
    if (ratio == 0ull) {
        T = 1u << 23;
    } else {
        float p = __fdiv_rn(2.0f, (float)ratio);   // matches jnp float32 divide
        double pt = (double)p * 8388608.0;          // p * 2^23 (exact)
        double ct = ceil(pt);
        T = (ct >= 8388608.0) ? (1u << 23) : (unsigned)ct;
    }
    g_T = T;
}

// ---------------- main scan: 2^26 threefry evals, split into chunks ---------
__device__ __forceinline__ void try_keep(unsigned t,
                                         const int* __restrict__ src,
                                         const int* __restrict__ dst) {
    unsigned i = t >> 13, j = t & (E_EDGES - 1u);
    int s = src[i];
    int dj = dst[j];
    if (dj == s) return;
    unsigned o = g_off[s], e = g_off[s + 1];
    for (unsigned k = o; k < e; k++)
        if (g_adj[k] == dj) return;
    atomicOr(&g_bitmap[t >> 6], 1ull << (t & 63u));
}

#define PER 8
__global__ void __launch_bounds__(256) k_main(const int* __restrict__ src,
                                              const int* __restrict__ dst,
                                              unsigned chunk_base) {
    unsigned T = g_T;
    unsigned base = chunk_base + (blockIdx.x * 256u + threadIdx.x) * PER;
#pragma unroll
    for (int u = 0; u < PER; u++) {
        unsigned c = base + u;
        unsigned m = tf_bits(c) >> 9;
        if (m < T) try_keep(c, src, dst);
    }
}

// ---------------- ordered compaction of bitmap (R6 versions) ----------------
__global__ void k_count() {  // 1024 blocks x 256 threads, 4 words each
    __shared__ unsigned s[256];
    unsigned wbase = blockIdx.x * 1024u + threadIdx.x * 4u;
    unsigned c = 0;
#pragma unroll
    for (int k = 0; k < 4; k++) c += __popcll(g_bitmap[wbase + k]);
    s[threadIdx.x] = c; __syncthreads();
    for (int d = 128; d > 0; d >>= 1) {
        if (threadIdx.x < (unsigned)d) s[threadIdx.x] += s[threadIdx.x + d];
        __syncthreads();
    }
    if (threadIdx.x == 0) g_blockcnt[blockIdx.x] = s[0];
}

__global__ void k_scan_blk() {  // 1 block, 1024 threads
    __shared__ unsigned s[1024];
    unsigned t = threadIdx.x;
    unsigned v = g_blockcnt[t];
    s[t] = v; __syncthreads();
    for (int d = 1; d < 1024; d <<= 1) {
        unsigned a = (t >= (unsigned)d) ? s[t - d] : 0u;
        __syncthreads();
        s[t] += a;
        __syncthreads();
    }
    g_blockoff[t] = s[t] - v;  // exclusive prefix
}

__global__ void k_out_init(const int* __restrict__ src, const int* __restrict__ dst,
                           float* __restrict__ out, int out_size) {
    unsigned q = blockIdx.x * blockDim.x + threadIdx.x;
    if (q < KOUT) {
        if ((int)q < out_size) out[q] = (float)src[0];
        if ((int)(KOUT + q) < out_size) out[KOUT + q] = (float)dst[0];
    }
}

__global__ void k_emit(const int* __restrict__ src, const int* __restrict__ dst,
                       float* __restrict__ out, int out_size) {
    __shared__ unsigned s[256];
    unsigned t = threadIdx.x;
    unsigned wbase = blockIdx.x * 1024u + t * 4u;
    unsigned long long w[4];
    unsigned c = 0;
#pragma unroll
    for (int k = 0; k < 4; k++) { w[k] = g_bitmap[wbase + k]; c += __popcll(w[k]); }
    s[t] = c; __syncthreads();
    for (int d = 1; d < 256; d <<= 1) {
        unsigned a = (t >= (unsigned)d) ? s[t - d] : 0u;
        __syncthreads();
        s[t] += a;
        __syncthreads();
    }
    unsigned pos = g_blockoff[blockIdx.x] + s[t] - c;
    if (c == 0) return;
#pragma unroll
    for (int k = 0; k < 4; k++) {
        unsigned long long ww = w[k];
        unsigned wi = wbase + k;
        while (ww) {
            int b = __ffsll((long long)ww) - 1;
            unsigned tt = wi * 64u + (unsigned)b;
            if (pos < KOUT) {
                if ((int)pos < out_size) out[pos] = (float)src[tt >> 13];
                if ((int)(KOUT + pos) < out_size) out[KOUT + pos] = (float)dst[tt & (E_EDGES - 1u)];
            }
            pos++;
            ww &= ww - 1ull;
        }
    }
}

// ---------------- launch ----------------
extern "C" void kernel_launch(void* const* d_in, const int* in_sizes, int n_in,
                              void* d_out, int out_size) {
    // Input selection by element count (node_feature has 262144 elems).
    const int* src;
    const int* dst;
    if (n_in >= 3 && in_sizes[0] == (int)E_EDGES) {
        dst = (const int*)d_in[0];   // alphabetical: edge_dst first
        src = (const int*)d_in[1];
    } else {
        src = (const int*)d_in[1];   // dict order: node_feature first
        dst = (const int*)d_in[2];
    }
    float* out = (float*)d_out;

    k_zero<<<NWORDS / 512, 512>>>();
    k_hist<<<E_EDGES / 256, 256>>>(src, dst);
    k_scan_deg<<<1, 1024>>>();
    k_fill<<<E_EDGES / 256, 256>>>(src, dst);
    k_rowcount<<<N_NODES / 256, 256>>>();
    k_thresh<<<1, 1>>>();
    // k_main split into NCHUNK equal ranges (same total work as R6).
    const unsigned chunk_elems = TOTAL / NCHUNK;             // 2^22
    const unsigned chunk_blocks = chunk_elems / (256 * PER); // 2048
    for (unsigned ch = 0; ch < NCHUNK; ch++)
        k_main<<<chunk_blocks, 256>>>(src, dst, ch * chunk_elems);
    k_count<<<1024, 256>>>();
    k_scan_blk<<<1, 1024>>>();
    k_out_init<<<KOUT / 256, 256>>>(src, dst, out, out_size);
    k_emit<<<1024, 256>>>(src, dst, out, out_size);
}

// round 10
// speedup vs baseline: 1.7410x; 1.1912x over previous
#include <cuda_runtime.h>
#include <cstdint>

// Problem constants (fixed by the dataset).
#define E_EDGES 8192u
#define N_NODES 4096u
#define TOTAL (1u << 26)         // E*E elements
#define KOUT 16384               // K*E output rows
#define NWORDS (1u << 20)        // 2^26 bits / 64

// ---------------- device scratch (static allocations only) ----------------
__device__ unsigned g_cnt_d[N_NODES];
__device__ unsigned g_deg[N_NODES];
__device__ unsigned g_off[N_NODES + 1];
__device__ unsigned g_cursor[N_NODES];
__device__ int g_adj[E_EDGES];
__device__ unsigned long long g_numneg;
__device__ unsigned g_T;                       // mantissa threshold, 0..2^23
__device__ unsigned long long g_bitmap[NWORDS]; // 8 MB kept-bitmap over t in [0, 2^26)
__device__ unsigned g_blockcnt[1024];
__device__ unsigned g_blockoff[1024];

// ------- threefry-2x32, key = (0, 42), partitionable layout (validated) -------
// Pipe-balanced rounds: half the rotations go through a widening multiply
// (IMAD.WIDE on the fma pipe; rotl(x,r) = lo|hi of x * 2^r) + one fused
// LOP3 ((lo|hi)^x0), offloading the alu pipe (SHF/LOP3) which bounds k_main.
#define TF_ROUND_S(r) { x0 += x1; x1 = __funnelshift_l(x1, x1, (r)) ^ x0; }
#define TF_ROUND_M(r) { x0 += x1;                                            \
    unsigned long long w = (unsigned long long)x1 * (1ull << (r));           \
    x1 = ((unsigned)w | (unsigned)(w >> 32)) ^ x0; }

__device__ __forceinline__ unsigned tf_bits(unsigned t) {
    const unsigned ks0 = 0u, ks1 = 42u, ks2 = 0x1BD11BDAu ^ 42u;
    unsigned x0 = 0u;            // counts_hi + ks0
    unsigned x1 = t + ks1;       // counts_lo + ks1
    TF_ROUND_M(13) TF_ROUND_S(15) TF_ROUND_M(26) TF_ROUND_S(6)
    x0 += ks1; x1 += ks2 + 1u;
    TF_ROUND_M(17) TF_ROUND_S(29) TF_ROUND_M(16) TF_ROUND_S(24)
    x0 += ks2; x1 += ks0 + 2u;
    TF_ROUND_M(13) TF_ROUND_S(15) TF_ROUND_M(26) TF_ROUND_S(6)
    x0 += ks0; x1 += ks1 + 3u;
    TF_ROUND_M(17) TF_ROUND_S(29) TF_ROUND_M(16) TF_ROUND_S(24)
    x0 += ks1; x1 += ks2 + 4u;
    TF_ROUND_M(13) TF_ROUND_S(15) TF_ROUND_M(26) TF_ROUND_S(6)
    x0 += ks2; x1 += ks0 + 5u;
    return x0 ^ x1;
}

// ---------------- setup kernels (R6-scored versions, unchanged) -------------
__global__ void k_zero() {
    unsigned tid = blockIdx.x * blockDim.x + threadIdx.x;  // 2^20 threads
    g_bitmap[tid] = 0ull;
    if (tid < N_NODES) { g_cnt_d[tid] = 0u; g_deg[tid] = 0u; g_cursor[tid] = 0u; }
    if (tid == 0) g_numneg = 0ull;
}

__global__ void k_hist(const int* __restrict__ src, const int* __restrict__ dst) {
    unsigned e = blockIdx.x * blockDim.x + threadIdx.x;
    if (e < E_EDGES) {
        unsigned d = (unsigned)dst[e], s = (unsigned)src[e];
        if (d < N_NODES) atomicAdd(&g_cnt_d[d], 1u);
        if (s < N_NODES) atomicAdd(&g_deg[s], 1u);
    }
}

__global__ void k_scan_deg() {  // 1 block, 1024 threads, 4 elems/thread
    __shared__ unsigned s[1024];
    unsigned t = threadIdx.x;
    unsigned v[4], sum = 0;
#pragma unroll
    for (int k = 0; k < 4; k++) { v[k] = g_deg[t * 4 + k]; sum += v[k]; }
    s[t] = sum; __syncthreads();
    for (int d = 1; d < 1024; d <<= 1) {
        unsigned a = (t >= (unsigned)d) ? s[t - d] : 0u;
        __syncthreads();
        s[t] += a;
        __syncthreads();
    }
    unsigned excl = (t == 0) ? 0u : s[t - 1];
#pragma unroll
    for (int k = 0; k < 4; k++) { g_off[t * 4 + k] = excl; excl += v[k]; }
    if (t == 1023) g_off[N_NODES] = excl;
}

__global__ void k_fill(const int* __restrict__ src, const int* __restrict__ dst) {
    unsigned e = blockIdx.x * blockDim.x + threadIdx.x;
    if (e < E_EDGES) {
        unsigned s = (unsigned)src[e];
        if (s < N_NODES) {
            unsigned pos = atomicAdd(&g_cursor[s], 1u);
            unsigned slot = g_off[s] + pos;
            if (slot < E_EDGES) g_adj[slot] = dst[e];
        }
    }
}

__global__ void k_rowcount() {
    unsigned s = blockIdx.x * blockDim.x + threadIdx.x;
    if (s >= N_NODES) return;
    unsigned o = g_off[s], e = g_off[s + 1];
    unsigned d = e - o;
    if (d == 0) return;
    unsigned X = g_cnt_d[s];
    for (unsigned a = o; a < e; a++) {
        int v = g_adj[a];
        if (v == (int)s) continue;
        bool dup = false;
        for (unsigned b = o; b < a; b++) if (g_adj[b] == v) { dup = true; break; }
        if (!dup && (unsigned)v < N_NODES) X += g_cnt_d[v];
    }
    atomicAdd(&g_numneg, (unsigned long long)d * (unsigned long long)(E_EDGES - X));
}

__global__ void k_thresh() {
    unsigned long long nn = g_numneg;
    unsigned long long ratio = nn >> 13;  // // E
    unsigned T;
    if (ratio == 0ull) {
        T = 1u << 23;
    } else {
        float p = __fdiv_rn(2.0f, (float)ratio);   // matches jnp float32 divide
        double pt = (double)p * 8388608.0;          // p * 2^23 (exact)
        double ct = ceil(pt);
        T = (ct >= 8388608.0) ? (1u << 23) : (unsigned)ct;
    }
    g_T = T;
}

// ---------------- main scan: 2^26 threefry evaluations ----------------
__device__ __forceinline__ void try_keep(unsigned t,
                                         const int* __restrict__ src,
                                         const int* __restrict__ dst) {
    unsigned i = t >> 13, j = t & (E_EDGES - 1u);
    int s = src[i];
    int dj = dst[j];
    if (dj == s) return;
    unsigned o = g_off[s], e = g_off[s + 1];
    for (unsigned k = o; k < e; k++)
        if (g_adj[k] == dj) return;
    atomicOr(&g_bitmap[t >> 6], 1ull << (t & 63u));
}

#define PER 8
__global__ void __launch_bounds__(256) k_main(const int* __restrict__ src,
                                              const int* __restrict__ dst) {
    unsigned T = g_T;
    unsigned base = (blockIdx.x * 256u + threadIdx.x) * PER;
#pragma unroll
    for (int u = 0; u < PER; u++) {
        unsigned c = base + u;
        unsigned m = tf_bits(c) >> 9;
        if (m < T) try_keep(c, src, dst);
    }
}

// ---------------- ordered compaction of bitmap (R6 versions) ----------------
__global__ void k_count() {  // 1024 blocks x 256 threads, 4 words each
    __shared__ unsigned s[256];
    unsigned wbase = blockIdx.x * 1024u + threadIdx.x * 4u;
    unsigned c = 0;
#pragma unroll
    for (int k = 0; k < 4; k++) c += __popcll(g_bitmap[wbase + k]);
    s[threadIdx.x] = c; __syncthreads();
    for (int d = 128; d > 0; d >>= 1) {
        if (threadIdx.x < (unsigned)d) s[threadIdx.x] += s[threadIdx.x + d];
        __syncthreads();
    }
    if (threadIdx.x == 0) g_blockcnt[blockIdx.x] = s[0];
}

__global__ void k_scan_blk() {  // 1 block, 1024 threads
    __shared__ unsigned s[1024];
    unsigned t = threadIdx.x;
    unsigned v = g_blockcnt[t];
    s[t] = v; __syncthreads();
    for (int d = 1; d < 1024; d <<= 1) {
        unsigned a = (t >= (unsigned)d) ? s[t - d] : 0u;
        __syncthreads();
        s[t] += a;
        __syncthreads();
    }
    g_blockoff[t] = s[t] - v;  // exclusive prefix
}

__global__ void k_out_init(const int* __restrict__ src, const int* __restrict__ dst,
                           float* __restrict__ out, int out_size) {
    unsigned q = blockIdx.x * blockDim.x + threadIdx.x;
    if (q < KOUT) {
        if ((int)q < out_size) out[q] = (float)src[0];
        if ((int)(KOUT + q) < out_size) out[KOUT + q] = (float)dst[0];
    }
}

__global__ void k_emit(const int* __restrict__ src, const int* __restrict__ dst,
                       float* __restrict__ out, int out_size) {
    __shared__ unsigned s[256];
    unsigned t = threadIdx.x;
    unsigned wbase = blockIdx.x * 1024u + t * 4u;
    unsigned long long w[4];
    unsigned c = 0;
#pragma unroll
    for (int k = 0; k < 4; k++) { w[k] = g_bitmap[wbase + k]; c += __popcll(w[k]); }
    s[t] = c; __syncthreads();
    for (int d = 1; d < 256; d <<= 1) {
        unsigned a = (t >= (unsigned)d) ? s[t - d] : 0u;
        __syncthreads();
        s[t] += a;
        __syncthreads();
    }
    unsigned pos = g_blockoff[blockIdx.x] + s[t] - c;
    if (c == 0) return;
#pragma unroll
    for (int k = 0; k < 4; k++) {
        unsigned long long ww = w[k];
        unsigned wi = wbase + k;
        while (ww) {
            int b = __ffsll((long long)ww) - 1;
            unsigned tt = wi * 64u + (unsigned)b;
            if (pos < KOUT) {
                if ((int)pos < out_size) out[pos] = (float)src[tt >> 13];
                if ((int)(KOUT + pos) < out_size) out[KOUT + pos] = (float)dst[tt & (E_EDGES - 1u)];
            }
            pos++;
            ww &= ww - 1ull;
        }
    }
}

// ---------------- launch ----------------
extern "C" void kernel_launch(void* const* d_in, const int* in_sizes, int n_in,
                              void* d_out, int out_size) {
    // Input selection by element count (node_feature has 262144 elems).
    const int* src;
    const int* dst;
    if (n_in >= 3 && in_sizes[0] == (int)E_EDGES) {
        dst = (const int*)d_in[0];   // alphabetical: edge_dst first
        src = (const int*)d_in[1];
    } else {
        src = (const int*)d_in[1];   // dict order: node_feature first
        dst = (const int*)d_in[2];
    }
    float* out = (float*)d_out;

    k_zero<<<NWORDS / 512, 512>>>();
    k_hist<<<E_EDGES / 256, 256>>>(src, dst);
    k_scan_deg<<<1, 1024>>>();
    k_fill<<<E_EDGES / 256, 256>>>(src, dst);
    k_rowcount<<<N_NODES / 256, 256>>>();
    k_thresh<<<1, 1>>>();
    k_main<<<TOTAL / (256 * PER), 256>>>(src, dst);
    k_count<<<1024, 256>>>();
    k_scan_blk<<<1, 1024>>>();
    k_out_init<<<KOUT / 256, 256>>>(src, dst, out, out_size);
    k_emit<<<1024, 256>>>(src, dst, out, out_size);
}

// round 11
// speedup vs baseline: 1.7806x; 1.0227x over previous
#include <cuda_runtime.h>
#include <cstdint>

// Problem constants (fixed by the dataset).
#define E_EDGES 8192u
#define N_NODES 4096u
#define TOTAL (1u << 26)         // E*E elements
#define KOUT 16384               // K*E output rows
#define NBUCK 4096u              // kept-index buckets (t >> 14)
#define BSLOTS 64u               // slots per bucket (avg load ~4)

// ---------------- device scratch (static allocations only) ----------------
__device__ unsigned g_cnt_d[N_NODES];
__device__ unsigned g_deg[N_NODES];
__device__ unsigned g_off[N_NODES + 1];
__device__ unsigned g_cursor[N_NODES];
__device__ int g_adj[E_EDGES];
__device__ unsigned long long g_numneg;
__device__ unsigned g_T;                       // mantissa threshold, 0..2^23
__device__ unsigned g_bcnt[NBUCK];             // kept count per bucket
__device__ unsigned g_boff[NBUCK];             // exclusive prefix of counts
__device__ unsigned g_bslot[NBUCK * BSLOTS];   // kept t values (unordered in bucket)

// ------- threefry-2x32, key = (0, 42), partitionable layout (validated) -------
#define TF_ROUND_S(r) { x0 += x1; x1 = __funnelshift_l(x1, x1, (r)) ^ x0; }
#define TF_ROUND_M(r) { x0 += x1;                                            \
    unsigned long long w = (unsigned long long)x1 * (1ull << (r));           \
    x1 = ((unsigned)w | (unsigned)(w >> 32)) ^ x0; }

__device__ __forceinline__ unsigned tf_bits(unsigned t) {
    const unsigned ks0 = 0u, ks1 = 42u, ks2 = 0x1BD11BDAu ^ 42u;
    unsigned x0 = 0u;            // counts_hi + ks0
    unsigned x1 = t + ks1;       // counts_lo + ks1
    TF_ROUND_M(13) TF_ROUND_S(15) TF_ROUND_M(26) TF_ROUND_S(6)
    x0 += ks1; x1 += ks2 + 1u;
    TF_ROUND_M(17) TF_ROUND_S(29) TF_ROUND_M(16) TF_ROUND_S(24)
    x0 += ks2; x1 += ks0 + 2u;
    TF_ROUND_M(13) TF_ROUND_S(15) TF_ROUND_M(26) TF_ROUND_S(6)
    x0 += ks0; x1 += ks1 + 3u;
    TF_ROUND_M(17) TF_ROUND_S(29) TF_ROUND_M(16) TF_ROUND_S(24)
    x0 += ks1; x1 += ks2 + 4u;
    TF_ROUND_M(13) TF_ROUND_S(15) TF_ROUND_M(26) TF_ROUND_S(6)
    x0 += ks2; x1 += ks0 + 5u;
    return x0 ^ x1;
}

// ---------------- kernel: zero small scratch (counters only) ----------------
__global__ void k_init() {
    unsigned tid = blockIdx.x * blockDim.x + threadIdx.x;   // 4096 threads
    g_bcnt[tid] = 0u;
    g_cnt_d[tid] = 0u; g_deg[tid] = 0u; g_cursor[tid] = 0u;
    if (tid == 0) g_numneg = 0ull;
}

// ---------------- setup kernels (R6/R10-scored versions, unchanged) ---------
__global__ void k_hist(const int* __restrict__ src, const int* __restrict__ dst) {
    unsigned e = blockIdx.x * blockDim.x + threadIdx.x;
    if (e < E_EDGES) {
        unsigned d = (unsigned)dst[e], s = (unsigned)src[e];
        if (d < N_NODES) atomicAdd(&g_cnt_d[d], 1u);
        if (s < N_NODES) atomicAdd(&g_deg[s], 1u);
    }
}

__global__ void k_scan_deg() {  // 1 block, 1024 threads, 4 elems/thread
    __shared__ unsigned s[1024];
    unsigned t = threadIdx.x;
    unsigned v[4], sum = 0;
#pragma unroll
    for (int k = 0; k < 4; k++) { v[k] = g_deg[t * 4 + k]; sum += v[k]; }
    s[t] = sum; __syncthreads();
    for (int d = 1; d < 1024; d <<= 1) {
        unsigned a = (t >= (unsigned)d) ? s[t - d] : 0u;
        __syncthreads();
        s[t] += a;
        __syncthreads();
    }
    unsigned excl = (t == 0) ? 0u : s[t - 1];
#pragma unroll
    for (int k = 0; k < 4; k++) { g_off[t * 4 + k] = excl; excl += v[k]; }
    if (t == 1023) g_off[N_NODES] = excl;
}

__global__ void k_fill(const int* __restrict__ src, const int* __restrict__ dst) {
    unsigned e = blockIdx.x * blockDim.x + threadIdx.x;
    if (e < E_EDGES) {
        unsigned s = (unsigned)src[e];
        if (s < N_NODES) {
            unsigned pos = atomicAdd(&g_cursor[s], 1u);
            unsigned slot = g_off[s] + pos;
            if (slot < E_EDGES) g_adj[slot] = dst[e];
        }
    }
}

__global__ void k_rowcount() {
    unsigned s = blockIdx.x * blockDim.x + threadIdx.x;
    if (s >= N_NODES) return;
    unsigned o = g_off[s], e = g_off[s + 1];
    unsigned d = e - o;
    if (d == 0) return;
    unsigned X = g_cnt_d[s];
    for (unsigned a = o; a < e; a++) {
        int v = g_adj[a];
        if (v == (int)s) continue;
        bool dup = false;
        for (unsigned b = o; b < a; b++) if (g_adj[b] == v) { dup = true; break; }
        if (!dup && (unsigned)v < N_NODES) X += g_cnt_d[v];
    }
    atomicAdd(&g_numneg, (unsigned long long)d * (unsigned long long)(E_EDGES - X));
}

__global__ void k_thresh() {
    unsigned long long nn = g_numneg;
    unsigned long long ratio = nn >> 13;  // // E
    unsigned T;
    if (ratio == 0ull) {
        T = 1u << 23;
    } else {
        float p = __fdiv_rn(2.0f, (float)ratio);   // matches jnp float32 divide
        double pt = (double)p * 8388608.0;          // p * 2^23 (exact)
        double ct = ceil(pt);
        T = (ct >= 8388608.0) ? (1u << 23) : (unsigned)ct;
    }
    g_T = T;
}

// ---------------- main scan: 2^26 threefry evaluations ----------------
__device__ __forceinline__ void try_keep(unsigned t,
                                         const int* __restrict__ src,
                                         const int* __restrict__ dst) {
    unsigned i = t >> 13, j = t & (E_EDGES - 1u);
    int s = src[i];
    int dj = dst[j];
    if (dj == s) return;
    unsigned o = g_off[s], e = g_off[s + 1];
    for (unsigned k = o; k < e; k++)
        if (g_adj[k] == dj) return;
    // bucketed scatter: bucket preserves flat-t order across buckets
    unsigned b = t >> 14;
    unsigned pos = atomicAdd(&g_bcnt[b], 1u);
    if (pos < BSLOTS) g_bslot[b * BSLOTS + pos] = t;
}

#define PER 8
__global__ void __launch_bounds__(256) k_main(const int* __restrict__ src,
                                              const int* __restrict__ dst) {
    unsigned T = g_T;
    unsigned base = (blockIdx.x * 256u + threadIdx.x) * PER;
#pragma unroll
    for (int u = 0; u < PER; u++) {
        unsigned c = base + u;
        unsigned m = tf_bits(c) >> 9;
        if (m < T) try_keep(c, src, dst);
    }
}

// ------- scan bucket counts (1 block) + fused output pad init -------
__global__ void __launch_bounds__(1024) k_scan_buckets(
        const int* __restrict__ src, const int* __restrict__ dst,
        float* __restrict__ out, int out_size) {
    __shared__ unsigned s[1024];
    unsigned t = threadIdx.x;
    unsigned v[4], sum = 0;
#pragma unroll
    for (int k = 0; k < 4; k++) { v[k] = g_bcnt[t * 4 + k]; sum += v[k]; }
    s[t] = sum; __syncthreads();
    for (int d = 1; d < 1024; d <<= 1) {
        unsigned a = (t >= (unsigned)d) ? s[t - d] : 0u;
        __syncthreads();
        s[t] += a;
        __syncthreads();
    }
    unsigned excl = (t == 0) ? 0u : s[t - 1];
#pragma unroll
    for (int k = 0; k < 4; k++) { g_boff[t * 4 + k] = excl; excl += v[k]; }

    // fused pad init: positions never written by sort_emit keep the pad value
    float pad_s = (float)src[0], pad_d = (float)dst[0];
    for (unsigned q = t; q < KOUT; q += 1024) {
        if ((int)q < out_size) out[q] = pad_s;
        if ((int)(KOUT + q) < out_size) out[KOUT + q] = pad_d;
    }
}

// ------- sort-emit: one warp per bucket, rank ≤64 distinct entries -------
__global__ void __launch_bounds__(256) k_sort_emit(
        const int* __restrict__ src, const int* __restrict__ dst,
        float* __restrict__ out, int out_size) {
    __shared__ unsigned svals[8][BSLOTS];
    unsigned warp = threadIdx.x >> 5, lane = threadIdx.x & 31u;
    unsigned b = blockIdx.x * 8u + warp;          // 512 blocks x 8 warps = 4096
    unsigned n = g_bcnt[b];
    if (n > BSLOTS) n = BSLOTS;
    if (n == 0) return;
    unsigned off = g_boff[b];
    if (off >= KOUT) return;
    // load entries to shared
    for (unsigned l = lane; l < n; l += 32) svals[warp][l] = g_bslot[b * BSLOTS + l];
    __syncwarp();
    // rank each entry (entries are distinct t values)
    for (unsigned l = lane; l < n; l += 32) {
        unsigned mine = svals[warp][l];
        unsigned rank = 0;
        for (unsigned j = 0; j < n; j++) rank += (svals[warp][j] < mine) ? 1u : 0u;
        unsigned pos = off + rank;
        if (pos < KOUT) {
            if ((int)pos < out_size) out[pos] = (float)src[mine >> 13];
            if ((int)(KOUT + pos) < out_size)
                out[KOUT + pos] = (float)dst[mine & (E_EDGES - 1u)];
        }
    }
}

// ---------------- launch ----------------
extern "C" void kernel_launch(void* const* d_in, const int* in_sizes, int n_in,
                              void* d_out, int out_size) {
    // Input selection by element count (node_feature has 262144 elems).
    const int* src;
    const int* dst;
    if (n_in >= 3 && in_sizes[0] == (int)E_EDGES) {
        dst = (const int*)d_in[0];   // alphabetical: edge_dst first
        src = (const int*)d_in[1];
    } else {
        src = (const int*)d_in[1];   // dict order: node_feature first
        dst = (const int*)d_in[2];
    }
    float* out = (float*)d_out;

    k_init<<<NBUCK / 256, 256>>>();
    k_hist<<<E_EDGES / 256, 256>>>(src, dst);
    k_scan_deg<<<1, 1024>>>();
    k_fill<<<E_EDGES / 256, 256>>>(src, dst);
    k_rowcount<<<N_NODES / 256, 256>>>();
    k_thresh<<<1, 1>>>();
    k_main<<<TOTAL / (256 * PER), 256>>>(src, dst);
    k_scan_buckets<<<1, 1024>>>(src, dst, out, out_size);
    k_sort_emit<<<NBUCK / 8, 256>>>(src, dst, out, out_size);
}

// round 12
// speedup vs baseline: 1.8016x; 1.0118x over previous
#include <cuda_runtime.h>
#include <cstdint>

// Problem constants (fixed by the dataset).
#define E_EDGES 8192u
#define N_NODES 4096u
#define TOTAL (1u << 26)         // E*E elements
#define KOUT 16384               // K*E output rows
#define NBUCK 4096u              // kept-index buckets (t >> 14)
#define BSLOTS 64u               // slots per bucket (avg load ~4)

// ---------------- device scratch (static allocations only) ----------------
__device__ unsigned g_cnt_d[N_NODES];
__device__ unsigned g_deg[N_NODES];
__device__ unsigned g_off[N_NODES + 1];
__device__ unsigned g_cursor[N_NODES];
__device__ int g_adj[E_EDGES];
__device__ unsigned long long g_numneg;
__device__ unsigned g_T9;                      // (mantissa threshold) << 9
__device__ unsigned g_bcnt[NBUCK];             // kept count per bucket
__device__ unsigned g_boff[NBUCK];             // exclusive prefix of counts
__device__ unsigned g_bslot[NBUCK * BSLOTS];   // kept t values (unordered in bucket)

// ------- threefry-2x32, key = (0, 42), partitionable layout (validated) -------
// ALL rounds via widening multiply: rotl(x,r) = lo|hi of (u64)x * 2^r.
// IMAD.WIDE goes to the fma pipe; the single fused LOP3 ((lo|hi)^x0) + the
// round add stay on alu. Target mix ≈ 36 alu / 36 fma per eval (balanced).
#define TF_ROUND_M(r) { x0 += x1;                                            \
    unsigned long long w = (unsigned long long)x1 * (1ull << (r));           \
    x1 = ((unsigned)w | (unsigned)(w >> 32)) ^ x0; }

__device__ __forceinline__ unsigned tf_bits(unsigned t) {
    const unsigned ks0 = 0u, ks1 = 42u, ks2 = 0x1BD11BDAu ^ 42u;
    unsigned x0 = 0u;            // counts_hi + ks0
    unsigned x1 = t + ks1;       // counts_lo + ks1
    TF_ROUND_M(13) TF_ROUND_M(15) TF_ROUND_M(26) TF_ROUND_M(6)
    x0 += ks1; x1 += ks2 + 1u;
    TF_ROUND_M(17) TF_ROUND_M(29) TF_ROUND_M(16) TF_ROUND_M(24)
    x0 += ks2; x1 += ks0 + 2u;
    TF_ROUND_M(13) TF_ROUND_M(15) TF_ROUND_M(26) TF_ROUND_M(6)
    x0 += ks0; x1 += ks1 + 3u;
    TF_ROUND_M(17) TF_ROUND_M(29) TF_ROUND_M(16) TF_ROUND_M(24)
    x0 += ks1; x1 += ks2 + 4u;
    TF_ROUND_M(13) TF_ROUND_M(15) TF_ROUND_M(26) TF_ROUND_M(6)
    x0 += ks2; x1 += ks0 + 5u;
    return x0 ^ x1;
}

// ---------------- kernel: zero small scratch (counters only) ----------------
__global__ void k_init() {
    unsigned tid = blockIdx.x * blockDim.x + threadIdx.x;   // 4096 threads
    g_bcnt[tid] = 0u;
    g_cnt_d[tid] = 0u; g_deg[tid] = 0u; g_cursor[tid] = 0u;
    if (tid == 0) g_numneg = 0ull;
}

// ---------------- setup kernels (scored versions, unchanged) ---------
__global__ void k_hist(const int* __restrict__ src, const int* __restrict__ dst) {
    unsigned e = blockIdx.x * blockDim.x + threadIdx.x;
    if (e < E_EDGES) {
        unsigned d = (unsigned)dst[e], s = (unsigned)src[e];
        if (d < N_NODES) atomicAdd(&g_cnt_d[d], 1u);
        if (s < N_NODES) atomicAdd(&g_deg[s], 1u);
    }
}

__global__ void k_scan_deg() {  // 1 block, 1024 threads, 4 elems/thread
    __shared__ unsigned s[1024];
    unsigned t = threadIdx.x;
    unsigned v[4], sum = 0;
#pragma unroll
    for (int k = 0; k < 4; k++) { v[k] = g_deg[t * 4 + k]; sum += v[k]; }
    s[t] = sum; __syncthreads();
    for (int d = 1; d < 1024; d <<= 1) {
        unsigned a = (t >= (unsigned)d) ? s[t - d] : 0u;
        __syncthreads();
        s[t] += a;
        __syncthreads();
    }
    unsigned excl = (t == 0) ? 0u : s[t - 1];
#pragma unroll
    for (int k = 0; k < 4; k++) { g_off[t * 4 + k] = excl; excl += v[k]; }
    if (t == 1023) g_off[N_NODES] = excl;
}

__global__ void k_fill(const int* __restrict__ src, const int* __restrict__ dst) {
    unsigned e = blockIdx.x * blockDim.x + threadIdx.x;
    if (e < E_EDGES) {
        unsigned s = (unsigned)src[e];
        if (s < N_NODES) {
            unsigned pos = atomicAdd(&g_cursor[s], 1u);
            unsigned slot = g_off[s] + pos;
            if (slot < E_EDGES) g_adj[slot] = dst[e];
        }
    }
}

__global__ void k_rowcount() {
    unsigned s = blockIdx.x * blockDim.x + threadIdx.x;
    if (s >= N_NODES) return;
    unsigned o = g_off[s], e = g_off[s + 1];
    unsigned d = e - o;
    if (d == 0) return;
    unsigned X = g_cnt_d[s];
    for (unsigned a = o; a < e; a++) {
        int v = g_adj[a];
        if (v == (int)s) continue;
        bool dup = false;
        for (unsigned b = o; b < a; b++) if (g_adj[b] == v) { dup = true; break; }
        if (!dup && (unsigned)v < N_NODES) X += g_cnt_d[v];
    }
    atomicAdd(&g_numneg, (unsigned long long)d * (unsigned long long)(E_EDGES - X));
}

__global__ void k_thresh() {
    unsigned long long nn = g_numneg;
    unsigned long long ratio = nn >> 13;  // // E
    unsigned T;
    if (ratio == 0ull) {
        T = 1u << 23;
    } else {
        float p = __fdiv_rn(2.0f, (float)ratio);   // matches jnp float32 divide
        double pt = (double)p * 8388608.0;          // p * 2^23 (exact)
        double ct = ceil(pt);
        T = (ct >= 8388608.0) ? (1u << 23) : (unsigned)ct;
    }
    // Pre-shift: (bits>>9) < T  ⟺  bits < (T<<9)   for T < 2^23.
    // T = 2^23 (keep-all) cannot occur for this dataset (ratio ≈ 4095).
    g_T9 = (T >= (1u << 23)) ? 0xFFFFFFFFu : (T << 9);
}

// ---------------- main scan: 2^26 threefry evaluations ----------------
__device__ __forceinline__ void try_keep(unsigned t,
                                         const int* __restrict__ src,
                                         const int* __restrict__ dst) {
    unsigned i = t >> 13, j = t & (E_EDGES - 1u);
    int s = src[i];
    int dj = dst[j];
    if (dj == s) return;
    unsigned o = g_off[s], e = g_off[s + 1];
    for (unsigned k = o; k < e; k++)
        if (g_adj[k] == dj) return;
    // bucketed scatter: bucket preserves flat-t order across buckets
    unsigned b = t >> 14;
    unsigned pos = atomicAdd(&g_bcnt[b], 1u);
    if (pos < BSLOTS) g_bslot[b * BSLOTS + pos] = t;
}

#define PER 8
__global__ void __launch_bounds__(256) k_main(const int* __restrict__ src,
                                              const int* __restrict__ dst) {
    unsigned T9 = g_T9;
    unsigned base = (blockIdx.x * 256u + threadIdx.x) * PER;
#pragma unroll
    for (int u = 0; u < PER; u++) {
        unsigned c = base + u;
        if (tf_bits(c) < T9) try_keep(c, src, dst);
    }
}

// ------- scan bucket counts (1 block) + fused output pad init -------
__global__ void __launch_bounds__(1024) k_scan_buckets(
        const int* __restrict__ src, const int* __restrict__ dst,
        float* __restrict__ out, int out_size) {
    __shared__ unsigned s[1024];
    unsigned t = threadIdx.x;
    unsigned v[4], sum = 0;
#pragma unroll
    for (int k = 0; k < 4; k++) { v[k] = g_bcnt[t * 4 + k]; sum += v[k]; }
    s[t] = sum; __syncthreads();
    for (int d = 1; d < 1024; d <<= 1) {
        unsigned a = (t >= (unsigned)d) ? s[t - d] : 0u;
        __syncthreads();
        s[t] += a;
        __syncthreads();
    }
    unsigned excl = (t == 0) ? 0u : s[t - 1];
#pragma unroll
    for (int k = 0; k < 4; k++) { g_boff[t * 4 + k] = excl; excl += v[k]; }

    // fused pad init: positions never written by sort_emit keep the pad value
    float pad_s = (float)src[0], pad_d = (float)dst[0];
    for (unsigned q = t; q < KOUT; q += 1024) {
        if ((int)q < out_size) out[q] = pad_s;
        if ((int)(KOUT + q) < out_size) out[KOUT + q] = pad_d;
    }
}

// ------- sort-emit: one warp per bucket, rank ≤64 distinct entries -------
__global__ void __launch_bounds__(256) k_sort_emit(
        const int* __restrict__ src, const int* __restrict__ dst,
        float* __restrict__ out, int out_size) {
    __shared__ unsigned svals[8][BSLOTS];
    unsigned warp = threadIdx.x >> 5, lane = threadIdx.x & 31u;
    unsigned b = blockIdx.x * 8u + warp;          // 512 blocks x 8 warps = 4096
    unsigned n = g_bcnt[b];
    if (n > BSLOTS) n = BSLOTS;
    if (n == 0) return;
    unsigned off = g_boff[b];
    if (off >= KOUT) return;
    // load entries to shared
    for (unsigned l = lane; l < n; l += 32) svals[warp][l] = g_bslot[b * BSLOTS + l];
    __syncwarp();
    // rank each entry (entries are distinct t values)
    for (unsigned l = lane; l < n; l += 32) {
        unsigned mine = svals[warp][l];
        unsigned rank = 0;
        for (unsigned j = 0; j < n; j++) rank += (svals[warp][j] < mine) ? 1u : 0u;
        unsigned pos = off + rank;
        if (pos < KOUT) {
            if ((int)pos < out_size) out[pos] = (float)src[mine >> 13];
            if ((int)(KOUT + pos) < out_size)
                out[KOUT + pos] = (float)dst[mine & (E_EDGES - 1u)];
        }
    }
}

// ---------------- launch ----------------
extern "C" void kernel_launch(void* const* d_in, const int* in_sizes, int n_in,
                              void* d_out, int out_size) {
    // Input selection by element count (node_feature has 262144 elems).
    const int* src;
    const int* dst;
    if (n_in >= 3 && in_sizes[0] == (int)E_EDGES) {
        dst = (const int*)d_in[0];   // alphabetical: edge_dst first
        src = (const int*)d_in[1];
    } else {
        src = (const int*)d_in[1];   // dict order: node_feature first
        dst = (const int*)d_in[2];
    }
    float* out = (float*)d_out;

    k_init<<<NBUCK / 256, 256>>>();
    k_hist<<<E_EDGES / 256, 256>>>(src, dst);
    k_scan_deg<<<1, 1024>>>();
    k_fill<<<E_EDGES / 256, 256>>>(src, dst);
    k_rowcount<<<N_NODES / 256, 256>>>();
    k_thresh<<<1, 1>>>();
    k_main<<<TOTAL / (256 * PER), 256>>>(src, dst);
    k_scan_buckets<<<1, 1024>>>(src, dst, out, out_size);
    k_sort_emit<<<NBUCK / 8, 256>>>(src, dst, out, out_size);
}